// round 3
// baseline (speedup 1.0000x reference)
#include <cuda_runtime.h>

#define T_STEPS 512
#define BATCH   64
#define HID     512
#define GATES3  1536
#define NB_REC  128
#define NT_REC  256
#define WROW    514   // float2 stride for W rows (padded)
#define HROW    516   // float stride for h rows (padded)

// ---------------- scratch (static device allocations; no cudaMalloc) ----------------
__device__ float g_xg[(size_t)T_STEPS * BATCH * GATES3]; // precomputed input gates
__device__ float g_y0[(size_t)T_STEPS * BATCH * HID];    // layer-0 output
__device__ float g_hx[2 * BATCH * HID];                  // ping-pong h exchange [parity][b][j]
__device__ unsigned g_flags[NB_REC];                     // per-block step flags
__device__ unsigned g_end_cnt[8];
__device__ volatile unsigned g_end_gen[8];

// ---------------- packed fp32x2 FMA (Blackwell FFMA2) ----------------
__device__ __forceinline__ float2 ffma2(float2 a, float2 b, float2 c) {
    float2 d;
    asm("fma.rn.f32x2 %0, %1, %2, %3;"
        : "=l"(reinterpret_cast<unsigned long long&>(d))
        : "l"(reinterpret_cast<unsigned long long&>(a)),
          "l"(reinterpret_cast<unsigned long long&>(b)),
          "l"(reinterpret_cast<unsigned long long&>(c)));
    return d;
}

__device__ __forceinline__ float sigmoidf_(float x) {
    return 1.f / (1.f + __expf(-x));
}

// ---------------- GEMM: out[M,N] = A[M,K] * W[N,K]^T + bias ----------------
// 128x128 tile, BK=16, 256 threads, register-pipelined gmem->smem, 2 blocks/SM.
__global__ void __launch_bounds__(256, 2) gemm_bias_kernel(
    const float* __restrict__ A, const float* __restrict__ W,
    const float* __restrict__ bias, float* __restrict__ out, int K)
{
    __shared__ float As[16 * 132];
    __shared__ float Bs[16 * 132];

    const int tid = threadIdx.x;
    const int m0 = blockIdx.y * 128;
    const int n0 = blockIdx.x * 128;
    const int tm = tid >> 4;
    const int tn = tid & 15;

    // per-thread staging coordinates (2 chunks of 256 threads cover 512 float4)
    int row_[2], c4_[2];
#pragma unroll
    for (int u = 0; u < 2; ++u) {
        int s = tid + u * 256;
        row_[u] = s >> 2;
        c4_[u]  = s & 3;
    }

    float2 c2[8][4];
#pragma unroll
    for (int i = 0; i < 8; ++i)
#pragma unroll
        for (int p = 0; p < 4; ++p) c2[i][p] = make_float2(0.f, 0.f);

    // preload tile 0 into regs
    float4 ra[2], rb[2];
#pragma unroll
    for (int u = 0; u < 2; ++u) {
        ra[u] = *(const float4*)(A + (size_t)(m0 + row_[u]) * K + c4_[u] * 4);
        rb[u] = *(const float4*)(W + (size_t)(n0 + row_[u]) * K + c4_[u] * 4);
    }

    for (int kt = 0; kt < K; kt += 16) {
        // commit staged regs to smem (transposed k-major)
#pragma unroll
        for (int u = 0; u < 2; ++u) {
            int row = row_[u], c4 = c4_[u];
            As[(c4 * 4 + 0) * 132 + row] = ra[u].x;
            As[(c4 * 4 + 1) * 132 + row] = ra[u].y;
            As[(c4 * 4 + 2) * 132 + row] = ra[u].z;
            As[(c4 * 4 + 3) * 132 + row] = ra[u].w;
            Bs[(c4 * 4 + 0) * 132 + row] = rb[u].x;
            Bs[(c4 * 4 + 1) * 132 + row] = rb[u].y;
            Bs[(c4 * 4 + 2) * 132 + row] = rb[u].z;
            Bs[(c4 * 4 + 3) * 132 + row] = rb[u].w;
        }
        __syncthreads();

        // issue next tile's gmem loads early (land during compute)
        if (kt + 16 < K) {
#pragma unroll
            for (int u = 0; u < 2; ++u) {
                ra[u] = *(const float4*)(A + (size_t)(m0 + row_[u]) * K + kt + 16 + c4_[u] * 4);
                rb[u] = *(const float4*)(W + (size_t)(n0 + row_[u]) * K + kt + 16 + c4_[u] * 4);
            }
        }

#pragma unroll
        for (int kb = 0; kb < 16; ++kb) {
            float4 a0 = *(const float4*)(As + kb * 132 + tm * 8);
            float4 a1 = *(const float4*)(As + kb * 132 + tm * 8 + 4);
            float4 b0 = *(const float4*)(Bs + kb * 132 + tn * 8);
            float4 b1 = *(const float4*)(Bs + kb * 132 + tn * 8 + 4);
            float av[8] = {a0.x, a0.y, a0.z, a0.w, a1.x, a1.y, a1.z, a1.w};
            float2 bp[4] = {make_float2(b0.x, b0.y), make_float2(b0.z, b0.w),
                            make_float2(b1.x, b1.y), make_float2(b1.z, b1.w)};
#pragma unroll
            for (int i = 0; i < 8; ++i) {
                float2 as = make_float2(av[i], av[i]);
#pragma unroll
                for (int p = 0; p < 4; ++p) c2[i][p] = ffma2(as, bp[p], c2[i][p]);
            }
        }
        __syncthreads();
    }

    const float4 bb0 = *(const float4*)(bias + n0 + tn * 8);
    const float4 bb1 = *(const float4*)(bias + n0 + tn * 8 + 4);
#pragma unroll
    for (int i = 0; i < 8; ++i) {
        int m = m0 + tm * 8 + i;
        float4 o0 = make_float4(c2[i][0].x + bb0.x, c2[i][0].y + bb0.y,
                                c2[i][1].x + bb0.z, c2[i][1].y + bb0.w);
        float4 o1 = make_float4(c2[i][2].x + bb1.x, c2[i][2].y + bb1.y,
                                c2[i][3].x + bb1.z, c2[i][3].y + bb1.w);
        float* dst = out + (size_t)m * GATES3 + n0 + tn * 8;
        *(float4*)(dst)     = o0;
        *(float4*)(dst + 4) = o1;
    }
}

// ---------------- persistent GRU recurrence ----------------
// 128 blocks = 16 col-groups x 8 batch-groups; 256 threads = (kk half, cp colpair, bsub batch).
// Each thread: 2 cols x 3 gates x k-half(256) for 1 batch; smem reduction across halves.
__global__ void __launch_bounds__(NT_REC, 1) gru_rec_kernel(
    const float* __restrict__ xg, const float* __restrict__ Whh,
    const float* __restrict__ bhh, float* __restrict__ y,
    float* __restrict__ hn_out)
{
    extern __shared__ float smem[];
    float2* Ws2 = (float2*)smem;                 // 48 rows x 514 float2
    float*  hs  = smem + 48 * WROW * 2;          // 8 rows x 516 floats
    float*  red = hs + 8 * HROW;                 // 128 x 6 floats

    const int tid  = threadIdx.x;
    const int bid  = blockIdx.x;
    const int cg   = bid & 15;
    const int grp  = bid >> 4;
    const int j0   = cg * 32;
    const int b0   = grp * 8;
    const int kk   = tid >> 7;       // 0..1 k-half
    const int rem  = tid & 127;
    const int cp   = rem >> 3;       // 0..15 col-pair
    const int bsub = rem & 7;        // 0..7 batch
    const int b    = b0 + bsub;
    const int jj   = j0 + cp * 2;

    // one-time: W_hh slice with column pairs interleaved
    for (int idx = tid; idx < 48 * 512; idx += NT_REC) {
        int row = idx >> 9;
        int k   = idx & 511;
        int g   = row >> 4;
        int cpp = row & 15;
        int col = j0 + cpp * 2;
        Ws2[row * WROW + k] = make_float2(
            Whh[(size_t)(g * HID + col) * HID + k],
            Whh[(size_t)(g * HID + col + 1) * HID + k]);
    }
    for (int idx = tid; idx < 8 * HROW; idx += NT_REC) hs[idx] = 0.f;

    const float2 bhr = *(const float2*)(bhh + jj);
    const float2 bhz = *(const float2*)(bhh + HID + jj);
    const float2 bhn = *(const float2*)(bhh + 2 * HID + jj);

    const int kbase = kk * 256;
    const float2* wr = Ws2 + cp * WROW + kbase;
    const float2* wz = Ws2 + (16 + cp) * WROW + kbase;
    const float2* wn = Ws2 + (32 + cp) * WROW + kbase;
    const float*  hb = hs + bsub * HROW + kbase;

    const size_t xofs = (size_t)b * GATES3 + jj;
    float2 xr = make_float2(0.f, 0.f), xz = xr, xn = xr;
    if (kk == 0) {
        xr = *(const float2*)(xg + xofs);
        xz = *(const float2*)(xg + xofs + HID);
        xn = *(const float2*)(xg + xofs + 2 * HID);
    }

    float2 hp = make_float2(0.f, 0.f);   // own h, kept in regs (kk==0 threads)
    __syncthreads();

    for (int t = 0; t < T_STEPS; ++t) {
        if (t > 0) {
            // group barrier: all 16 blocks of this group posted step t
            if (tid < 16) {
                const unsigned* fp = &g_flags[grp * 16 + tid];
                unsigned v;
                do {
                    asm volatile("ld.acquire.gpu.global.u32 %0, [%1];" : "=r"(v) : "l"(fp));
                } while (v < (unsigned)t);
            }
            __syncthreads();
            // stage 16 KB of h for this group's 8 batches
            const float* hsrc = g_hx + (size_t)(t & 1) * BATCH * HID;
#pragma unroll
            for (int i = 0; i < 4; ++i) {
                int idx = tid + i * 256;
                int bb  = idx >> 7;
                int kq  = idx & 127;
                float4 v = __ldcg((const float4*)(hsrc + (size_t)(b0 + bb) * HID + kq * 4));
                *(float4*)(hs + bb * HROW + kq * 4) = v;
            }
            __syncthreads();
        }

        // half-k dot: 2 cols x 3 gates x 1 batch
        float2 ar = {0, 0}, az = {0, 0}, an = {0, 0};
        float2 ar2 = {0, 0}, az2 = {0, 0}, an2 = {0, 0};
#pragma unroll 4
        for (int k = 0; k < 256; k += 4) {
            float4 hv  = *(const float4*)(hb + k);
            float4 r01 = *(const float4*)(wr + k);
            float4 r23 = *(const float4*)(wr + k + 2);
            float4 z01 = *(const float4*)(wz + k);
            float4 z23 = *(const float4*)(wz + k + 2);
            float4 n01 = *(const float4*)(wn + k);
            float4 n23 = *(const float4*)(wn + k + 2);
            ar  = ffma2(make_float2(r01.x, r01.y), make_float2(hv.x, hv.x), ar);
            az  = ffma2(make_float2(z01.x, z01.y), make_float2(hv.x, hv.x), az);
            an  = ffma2(make_float2(n01.x, n01.y), make_float2(hv.x, hv.x), an);
            ar2 = ffma2(make_float2(r01.z, r01.w), make_float2(hv.y, hv.y), ar2);
            az2 = ffma2(make_float2(z01.z, z01.w), make_float2(hv.y, hv.y), az2);
            an2 = ffma2(make_float2(n01.z, n01.w), make_float2(hv.y, hv.y), an2);
            ar  = ffma2(make_float2(r23.x, r23.y), make_float2(hv.z, hv.z), ar);
            az  = ffma2(make_float2(z23.x, z23.y), make_float2(hv.z, hv.z), az);
            an  = ffma2(make_float2(n23.x, n23.y), make_float2(hv.z, hv.z), an);
            ar2 = ffma2(make_float2(r23.z, r23.w), make_float2(hv.w, hv.w), ar2);
            az2 = ffma2(make_float2(z23.z, z23.w), make_float2(hv.w, hv.w), az2);
            an2 = ffma2(make_float2(n23.z, n23.w), make_float2(hv.w, hv.w), an2);
        }
        ar.x += ar2.x; ar.y += ar2.y;
        az.x += az2.x; az.y += az2.y;
        an.x += an2.x; an.y += an2.y;

        // cross-half reduction
        if (kk == 1) {
            float2* r2 = (float2*)(red + rem * 6);
            r2[0] = ar; r2[1] = az; r2[2] = an;
        }
        __syncthreads();

        if (kk == 0) {
            const float2* r2 = (const float2*)(red + rem * 6);
            float2 pr = r2[0], pz = r2[1], pn = r2[2];
            float hrx = ar.x + pr.x + bhr.x, hry = ar.y + pr.y + bhr.y;
            float hzx = az.x + pz.x + bhz.x, hzy = az.y + pz.y + bhz.y;
            float hnx = an.x + pn.x + bhn.x, hny = an.y + pn.y + bhn.y;

            float rX = sigmoidf_(xr.x + hrx), rY = sigmoidf_(xr.y + hry);
            float zX = sigmoidf_(xz.x + hzx), zY = sigmoidf_(xz.y + hzy);
            float nX = tanhf(xn.x + rX * hnx), nY = tanhf(xn.y + rY * hny);
            float hX = (1.f - zX) * nX + zX * hp.x;
            float hY = (1.f - zY) * nY + zY * hp.y;
            hp = make_float2(hX, hY);

            // publish h slice FIRST (critical path)
            float* hdst = g_hx + (size_t)((t + 1) & 1) * BATCH * HID + (size_t)b * HID + jj;
            *(float2*)hdst = hp;
        }
        __syncthreads();
        if (tid == 0 && t < T_STEPS - 1) {
            __threadfence();
            asm volatile("st.global.cg.u32 [%0], %1;"
                         :: "l"(&g_flags[bid]), "r"((unsigned)(t + 1)) : "memory");
        }

        // off critical path: y store, hn store, next xg prefetch
        if (kk == 0) {
            *(float2*)(y + ((size_t)t * BATCH + b) * HID + jj) = hp;
            if (t == T_STEPS - 1) {
                *(float2*)(hn_out + (size_t)b * HID + jj) = hp;
            } else {
                const float* xp = xg + (size_t)(t + 1) * BATCH * GATES3 + xofs;
                xr = *(const float2*)(xp);
                xz = *(const float2*)(xp + HID);
                xn = *(const float2*)(xp + 2 * HID);
            }
        }
    }

    // end-of-launch: group gen-barrier (replay-safe), reset own flag
    __syncthreads();
    if (tid == 0) {
        unsigned gen = g_end_gen[grp];
        __threadfence();
        if (atomicAdd(&g_end_cnt[grp], 1u) == 15u) {
            g_end_cnt[grp] = 0u;
            __threadfence();
            g_end_gen[grp] = gen + 1u;
        } else {
            while (g_end_gen[grp] == gen) { __nanosleep(32); }
        }
        g_flags[bid] = 0u;
        __threadfence();
    }
}

// ---------------- launch ----------------
extern "C" void kernel_launch(void* const* d_in, const int* in_sizes, int n_in,
                              void* d_out, int out_size) {
    const float* x    = (const float*)d_in[0];
    const float* Wih0 = (const float*)d_in[1];
    const float* Whh0 = (const float*)d_in[2];
    const float* bih0 = (const float*)d_in[3];
    const float* bhh0 = (const float*)d_in[4];
    const float* Wih1 = (const float*)d_in[5];
    const float* Whh1 = (const float*)d_in[6];
    const float* bih1 = (const float*)d_in[7];
    const float* bhh1 = (const float*)d_in[8];

    float* out = (float*)d_out;
    float* y1  = out;
    float* hn0 = out + (size_t)T_STEPS * BATCH * HID;
    float* hn1 = hn0 + BATCH * HID;

    float *xg, *y0;
    cudaGetSymbolAddress((void**)&xg, g_xg);
    cudaGetSymbolAddress((void**)&y0, g_y0);

    const int rec_smem = (48 * WROW * 2 + 8 * HROW + 128 * 6) * 4;  // 219,936 B
    cudaFuncSetAttribute(gru_rec_kernel, cudaFuncAttributeMaxDynamicSharedMemorySize, rec_smem);

    dim3 ggrid(12, 256);

    gemm_bias_kernel<<<ggrid, 256>>>(x, Wih0, bih0, xg, 256);
    gru_rec_kernel<<<NB_REC, NT_REC, rec_smem>>>(xg, Whh0, bhh0, y0, hn0);
    gemm_bias_kernel<<<ggrid, 256>>>(y0, Wih1, bih1, xg, 512);
    gru_rec_kernel<<<NB_REC, NT_REC, rec_smem>>>(xg, Whh1, bhh1, y1, hn1);
}

// round 4
// speedup vs baseline: 1.3363x; 1.3363x over previous
#include <cuda_runtime.h>

#define T_STEPS 512
#define BATCH   64
#define HID     512
#define GATES3  1536
#define NB_REC  128
#define NT_REC  384
#define WROW    514   // float2 stride for W rows (padded)
#define HROW    516   // float stride for h rows (padded)

// ---------------- scratch (static device allocations; no cudaMalloc) ----------------
__device__ float g_xg[(size_t)T_STEPS * BATCH * GATES3]; // precomputed input gates
__device__ float g_y0[(size_t)T_STEPS * BATCH * HID];    // layer-0 output
__device__ float g_hx[2 * BATCH * HID];                  // ping-pong h exchange [parity][b][j]
__device__ unsigned g_flags[NB_REC];                     // per-block step flags
__device__ unsigned g_end_cnt[8];
__device__ volatile unsigned g_end_gen[8];

// ---------------- packed fp32x2 FMA (Blackwell FFMA2) ----------------
__device__ __forceinline__ float2 ffma2(float2 a, float2 b, float2 c) {
    float2 d;
    asm("fma.rn.f32x2 %0, %1, %2, %3;"
        : "=l"(reinterpret_cast<unsigned long long&>(d))
        : "l"(reinterpret_cast<unsigned long long&>(a)),
          "l"(reinterpret_cast<unsigned long long&>(b)),
          "l"(reinterpret_cast<unsigned long long&>(c)));
    return d;
}

__device__ __forceinline__ float sigmoidf_(float x) {
    return 1.f / (1.f + __expf(-x));
}

// ---------------- GEMM: out[M,N] = A[M,K] * W[N,K]^T + bias (R2 version, known-good) ----
__global__ void __launch_bounds__(256) gemm_bias_kernel(
    const float* __restrict__ A, const float* __restrict__ W,
    const float* __restrict__ bias, float* __restrict__ out, int K)
{
    __shared__ float As[16 * 132];
    __shared__ float Bs[16 * 132];

    const int tid = threadIdx.x;
    const int m0 = blockIdx.y * 128;
    const int n0 = blockIdx.x * 128;
    const int tm = tid >> 4;
    const int tn = tid & 15;

    float2 c2[8][4];
#pragma unroll
    for (int i = 0; i < 8; ++i)
#pragma unroll
        for (int p = 0; p < 4; ++p) c2[i][p] = make_float2(0.f, 0.f);

    for (int kt = 0; kt < K; kt += 16) {
#pragma unroll
        for (int u = 0; u < 2; ++u) {
            int s   = tid + u * 256;
            int row = s >> 2;
            int c4  = s & 3;
            float4 av = *(const float4*)(A + (size_t)(m0 + row) * K + kt + c4 * 4);
            As[(c4 * 4 + 0) * 132 + row] = av.x;
            As[(c4 * 4 + 1) * 132 + row] = av.y;
            As[(c4 * 4 + 2) * 132 + row] = av.z;
            As[(c4 * 4 + 3) * 132 + row] = av.w;
            float4 bv = *(const float4*)(W + (size_t)(n0 + row) * K + kt + c4 * 4);
            Bs[(c4 * 4 + 0) * 132 + row] = bv.x;
            Bs[(c4 * 4 + 1) * 132 + row] = bv.y;
            Bs[(c4 * 4 + 2) * 132 + row] = bv.z;
            Bs[(c4 * 4 + 3) * 132 + row] = bv.w;
        }
        __syncthreads();

#pragma unroll
        for (int kb = 0; kb < 16; ++kb) {
            float4 a0 = *(const float4*)(As + kb * 132 + tm * 8);
            float4 a1 = *(const float4*)(As + kb * 132 + tm * 8 + 4);
            float4 b0 = *(const float4*)(Bs + kb * 132 + tn * 8);
            float4 b1 = *(const float4*)(Bs + kb * 132 + tn * 8 + 4);
            float av[8] = {a0.x, a0.y, a0.z, a0.w, a1.x, a1.y, a1.z, a1.w};
            float2 bp[4] = {make_float2(b0.x, b0.y), make_float2(b0.z, b0.w),
                            make_float2(b1.x, b1.y), make_float2(b1.z, b1.w)};
#pragma unroll
            for (int i = 0; i < 8; ++i) {
                float2 as = make_float2(av[i], av[i]);
#pragma unroll
                for (int p = 0; p < 4; ++p) c2[i][p] = ffma2(as, bp[p], c2[i][p]);
            }
        }
        __syncthreads();
    }

    const float4 bb0 = *(const float4*)(bias + n0 + tn * 8);
    const float4 bb1 = *(const float4*)(bias + n0 + tn * 8 + 4);
#pragma unroll
    for (int i = 0; i < 8; ++i) {
        int m = m0 + tm * 8 + i;
        float4 o0 = make_float4(c2[i][0].x + bb0.x, c2[i][0].y + bb0.y,
                                c2[i][1].x + bb0.z, c2[i][1].y + bb0.w);
        float4 o1 = make_float4(c2[i][2].x + bb1.x, c2[i][2].y + bb1.y,
                                c2[i][3].x + bb1.z, c2[i][3].y + bb1.w);
        float* dst = out + (size_t)m * GATES3 + n0 + tn * 8;
        *(float4*)(dst)     = o0;
        *(float4*)(dst + 4) = o1;
    }
}

// ---------------- persistent GRU recurrence ----------------
// 128 blocks = 16 col-groups x 8 batch-groups.
// 384 threads = 3 gates x 16 col-pairs x 8 batches.
// Each thread: 1 gate, 2 cols, 1 batch, FULL k=512 dot (no k reduction).
__global__ void __launch_bounds__(NT_REC, 1) gru_rec_kernel(
    const float* __restrict__ xg, const float* __restrict__ Whh,
    const float* __restrict__ bhh, float* __restrict__ y,
    float* __restrict__ hn_out)
{
    extern __shared__ float smem[];
    float2* Ws2 = (float2*)smem;                 // 48 rows x 514 float2
    float*  hs  = smem + 48 * WROW * 2;          // 8 rows x 516 floats
    float2* red = (float2*)(hs + 8 * HROW);      // [2][128] float2 (z,n results w/ bias)

    const int tid  = threadIdx.x;
    const int bid  = blockIdx.x;
    const int cg   = bid & 15;
    const int grp  = bid >> 4;
    const int j0   = cg * 32;
    const int b0   = grp * 8;
    const int g    = tid >> 7;       // 0..2 gate (r,z,n)
    const int rem  = tid & 127;
    const int cp   = rem >> 3;       // 0..15 col-pair
    const int bsub = rem & 7;        // 0..7 batch
    const int b    = b0 + bsub;
    const int jj   = j0 + cp * 2;

    // one-time: W_hh slice, column pairs interleaved: Ws2[g*16+cp][k]=(W[j][k],W[j+1][k])
    for (int idx = tid; idx < 48 * 512; idx += NT_REC) {
        int row = idx >> 9;
        int k   = idx & 511;
        int gg  = row >> 4;
        int cpp = row & 15;
        int col = j0 + cpp * 2;
        Ws2[row * WROW + k] = make_float2(
            Whh[(size_t)(gg * HID + col) * HID + k],
            Whh[(size_t)(gg * HID + col + 1) * HID + k]);
    }
    for (int idx = tid; idx < 8 * HROW; idx += NT_REC) hs[idx] = 0.f;

    const float2 bh = *(const float2*)(bhh + g * HID + jj);   // own gate bias
    const float2* w  = Ws2 + (g * 16 + cp) * WROW;
    const float*  hb = hs + bsub * HROW;

    const size_t xofs = (size_t)b * GATES3 + jj;
    float2 xr = make_float2(0.f, 0.f), xz = xr, xn = xr;
    if (g == 0) {
        xr = *(const float2*)(xg + xofs);
        xz = *(const float2*)(xg + xofs + HID);
        xn = *(const float2*)(xg + xofs + 2 * HID);
    }

    float2 hp = make_float2(0.f, 0.f);   // own h (kept in g==0 threads)
    __syncthreads();

    for (int t = 0; t < T_STEPS; ++t) {
        if (t > 0) {
            if (tid < 16) {
                const unsigned* fp = &g_flags[grp * 16 + tid];
                unsigned v;
                do {
                    asm volatile("ld.acquire.gpu.global.u32 %0, [%1];" : "=r"(v) : "l"(fp));
                } while (v < (unsigned)t);
            }
            __syncthreads();
            const float* hsrc = g_hx + (size_t)(t & 1) * BATCH * HID;
#pragma unroll
            for (int i = 0; i < 3; ++i) {
                int idx = tid + i * NT_REC;
                if (idx < 1024) {
                    int bb  = idx >> 7;
                    int kq  = idx & 127;
                    float4 v = __ldcg((const float4*)(hsrc + (size_t)(b0 + bb) * HID + kq * 4));
                    *(float4*)(hs + bb * HROW + kq * 4) = v;
                }
            }
            __syncthreads();
        }

        // full-k dot: 2 cols x 1 gate x 1 batch; 4 independent FFMA2 chains
        float2 a0 = {0, 0}, a1 = {0, 0}, a2 = {0, 0}, a3 = {0, 0};
#pragma unroll 8
        for (int k = 0; k < HID; k += 4) {
            float4 hv  = *(const float4*)(hb + k);
            float4 w01 = *(const float4*)(w + k);
            float4 w23 = *(const float4*)(w + k + 2);
            a0 = ffma2(make_float2(w01.x, w01.y), make_float2(hv.x, hv.x), a0);
            a1 = ffma2(make_float2(w01.z, w01.w), make_float2(hv.y, hv.y), a1);
            a2 = ffma2(make_float2(w23.x, w23.y), make_float2(hv.z, hv.z), a2);
            a3 = ffma2(make_float2(w23.z, w23.w), make_float2(hv.w, hv.w), a3);
        }
        float2 acc = make_float2(a0.x + a1.x + a2.x + a3.x + bh.x,
                                 a0.y + a1.y + a2.y + a3.y + bh.y);

        // gate exchange: z,n threads publish (bias included); r threads finalize
        if (g > 0) red[(g - 1) * 128 + rem] = acc;
        __syncthreads();

        if (g == 0) {
            float2 hz = red[rem];
            float2 hn = red[128 + rem];
            float rX = sigmoidf_(xr.x + acc.x), rY = sigmoidf_(xr.y + acc.y);
            float zX = sigmoidf_(xz.x + hz.x),  zY = sigmoidf_(xz.y + hz.y);
            float nX = tanhf(xn.x + rX * hn.x), nY = tanhf(xn.y + rY * hn.y);
            float hX = (1.f - zX) * nX + zX * hp.x;
            float hY = (1.f - zY) * nY + zY * hp.y;
            hp = make_float2(hX, hY);

            float* hdst = g_hx + (size_t)((t + 1) & 1) * BATCH * HID + (size_t)b * HID + jj;
            *(float2*)hdst = hp;
        }
        __syncthreads();
        if (tid == 0 && t < T_STEPS - 1) {
            __threadfence();
            asm volatile("st.global.cg.u32 [%0], %1;"
                         :: "l"(&g_flags[bid]), "r"((unsigned)(t + 1)) : "memory");
        }

        // off critical path
        if (g == 0) {
            *(float2*)(y + ((size_t)t * BATCH + b) * HID + jj) = hp;
            if (t == T_STEPS - 1) {
                *(float2*)(hn_out + (size_t)b * HID + jj) = hp;
            } else {
                const float* xp = xg + (size_t)(t + 1) * BATCH * GATES3 + xofs;
                xr = *(const float2*)(xp);
                xz = *(const float2*)(xp + HID);
                xn = *(const float2*)(xp + 2 * HID);
            }
        }
    }

    __syncthreads();
    if (tid == 0) {
        unsigned gen = g_end_gen[grp];
        __threadfence();
        if (atomicAdd(&g_end_cnt[grp], 1u) == 15u) {
            g_end_cnt[grp] = 0u;
            __threadfence();
            g_end_gen[grp] = gen + 1u;
        } else {
            while (g_end_gen[grp] == gen) { __nanosleep(32); }
        }
        g_flags[bid] = 0u;
        __threadfence();
    }
}

// ---------------- launch ----------------
extern "C" void kernel_launch(void* const* d_in, const int* in_sizes, int n_in,
                              void* d_out, int out_size) {
    const float* x    = (const float*)d_in[0];
    const float* Wih0 = (const float*)d_in[1];
    const float* Whh0 = (const float*)d_in[2];
    const float* bih0 = (const float*)d_in[3];
    const float* bhh0 = (const float*)d_in[4];
    const float* Wih1 = (const float*)d_in[5];
    const float* Whh1 = (const float*)d_in[6];
    const float* bih1 = (const float*)d_in[7];
    const float* bhh1 = (const float*)d_in[8];

    float* out = (float*)d_out;
    float* y1  = out;
    float* hn0 = out + (size_t)T_STEPS * BATCH * HID;
    float* hn1 = hn0 + BATCH * HID;

    float *xg, *y0;
    cudaGetSymbolAddress((void**)&xg, g_xg);
    cudaGetSymbolAddress((void**)&y0, g_y0);

    const int rec_smem = (48 * WROW * 2 + 8 * HROW) * 4 + 256 * 8;  // 215,936 B
    cudaFuncSetAttribute(gru_rec_kernel, cudaFuncAttributeMaxDynamicSharedMemorySize, rec_smem);

    dim3 ggrid(12, 256);

    gemm_bias_kernel<<<ggrid, 256>>>(x, Wih0, bih0, xg, 256);
    gru_rec_kernel<<<NB_REC, NT_REC, rec_smem>>>(xg, Whh0, bhh0, y0, hn0);
    gemm_bias_kernel<<<ggrid, 256>>>(y0, Wih1, bih1, xg, 512);
    gru_rec_kernel<<<NB_REC, NT_REC, rec_smem>>>(xg, Whh1, bhh1, y1, hn1);
}

// round 5
// speedup vs baseline: 1.4914x; 1.1161x over previous
#include <cuda_runtime.h>

#define T_STEPS 512
#define BATCH   64
#define HID     512
#define GATES3  1536
#define NB_REC  128
#define NT_REC  256
#define WR      516   // float stride for smem rows (padded: conflict-free)

// ---------------- scratch (static device allocations; no cudaMalloc) ----------------
__device__ float g_xg[(size_t)T_STEPS * BATCH * GATES3]; // precomputed input gates
__device__ float g_y0[(size_t)T_STEPS * BATCH * HID];    // layer-0 output
__device__ float g_hx[2 * BATCH * HID];                  // ping-pong h exchange [parity][b][j]
__device__ unsigned g_flags[NB_REC];                     // per-block step flags
__device__ unsigned g_end_cnt[8];
__device__ volatile unsigned g_end_gen[8];

// ---------------- packed fp32x2 FMA (Blackwell FFMA2) ----------------
__device__ __forceinline__ float2 ffma2(float2 a, float2 b, float2 c) {
    float2 d;
    asm("fma.rn.f32x2 %0, %1, %2, %3;"
        : "=l"(reinterpret_cast<unsigned long long&>(d))
        : "l"(reinterpret_cast<unsigned long long&>(a)),
          "l"(reinterpret_cast<unsigned long long&>(b)),
          "l"(reinterpret_cast<unsigned long long&>(c)));
    return d;
}

__device__ __forceinline__ float sigmoidf_(float x) {
    return 1.f / (1.f + __expf(-x));
}

// ---------------- GEMM: out[M,N] = A[M,K] * W[N,K]^T + bias (R2 version, known-good) ----
__global__ void __launch_bounds__(256) gemm_bias_kernel(
    const float* __restrict__ A, const float* __restrict__ W,
    const float* __restrict__ bias, float* __restrict__ out, int K)
{
    __shared__ float As[16 * 132];
    __shared__ float Bs[16 * 132];

    const int tid = threadIdx.x;
    const int m0 = blockIdx.y * 128;
    const int n0 = blockIdx.x * 128;
    const int tm = tid >> 4;
    const int tn = tid & 15;

    float2 c2[8][4];
#pragma unroll
    for (int i = 0; i < 8; ++i)
#pragma unroll
        for (int p = 0; p < 4; ++p) c2[i][p] = make_float2(0.f, 0.f);

    for (int kt = 0; kt < K; kt += 16) {
#pragma unroll
        for (int u = 0; u < 2; ++u) {
            int s   = tid + u * 256;
            int row = s >> 2;
            int c4  = s & 3;
            float4 av = *(const float4*)(A + (size_t)(m0 + row) * K + kt + c4 * 4);
            As[(c4 * 4 + 0) * 132 + row] = av.x;
            As[(c4 * 4 + 1) * 132 + row] = av.y;
            As[(c4 * 4 + 2) * 132 + row] = av.z;
            As[(c4 * 4 + 3) * 132 + row] = av.w;
            float4 bv = *(const float4*)(W + (size_t)(n0 + row) * K + kt + c4 * 4);
            Bs[(c4 * 4 + 0) * 132 + row] = bv.x;
            Bs[(c4 * 4 + 1) * 132 + row] = bv.y;
            Bs[(c4 * 4 + 2) * 132 + row] = bv.z;
            Bs[(c4 * 4 + 3) * 132 + row] = bv.w;
        }
        __syncthreads();

#pragma unroll
        for (int kb = 0; kb < 16; ++kb) {
            float4 a0 = *(const float4*)(As + kb * 132 + tm * 8);
            float4 a1 = *(const float4*)(As + kb * 132 + tm * 8 + 4);
            float4 b0 = *(const float4*)(Bs + kb * 132 + tn * 8);
            float4 b1 = *(const float4*)(Bs + kb * 132 + tn * 8 + 4);
            float av[8] = {a0.x, a0.y, a0.z, a0.w, a1.x, a1.y, a1.z, a1.w};
            float2 bp[4] = {make_float2(b0.x, b0.y), make_float2(b0.z, b0.w),
                            make_float2(b1.x, b1.y), make_float2(b1.z, b1.w)};
#pragma unroll
            for (int i = 0; i < 8; ++i) {
                float2 as = make_float2(av[i], av[i]);
#pragma unroll
                for (int p = 0; p < 4; ++p) c2[i][p] = ffma2(as, bp[p], c2[i][p]);
            }
        }
        __syncthreads();
    }

    const float4 bb0 = *(const float4*)(bias + n0 + tn * 8);
    const float4 bb1 = *(const float4*)(bias + n0 + tn * 8 + 4);
#pragma unroll
    for (int i = 0; i < 8; ++i) {
        int m = m0 + tm * 8 + i;
        float4 o0 = make_float4(c2[i][0].x + bb0.x, c2[i][0].y + bb0.y,
                                c2[i][1].x + bb0.z, c2[i][1].y + bb0.w);
        float4 o1 = make_float4(c2[i][2].x + bb1.x, c2[i][2].y + bb1.y,
                                c2[i][3].x + bb1.z, c2[i][3].y + bb1.w);
        float* dst = out + (size_t)m * GATES3 + n0 + tn * 8;
        *(float4*)(dst)     = o0;
        *(float4*)(dst + 4) = o1;
    }
}

// ---------------- persistent GRU recurrence ----------------
// 128 blocks = 16 col-groups x 8 batch-groups.
// 256 threads = 32 cols x 8 batches. Each thread: 1 col, ALL 3 gates, 1 batch,
// full k=512 with FFMA2 packed ALONG K. No reductions, no gate exchange:
// every thread finalizes its own (col,batch) h value.
__global__ void __launch_bounds__(NT_REC, 1) gru_rec_kernel(
    const float* __restrict__ xg, const float* __restrict__ Whh,
    const float* __restrict__ bhh, float* __restrict__ y,
    float* __restrict__ hn_out)
{
    extern __shared__ float smem[];
    float* Ws = smem;                 // 96 rows (g*32+col) x 516 floats
    float* hs = smem + 96 * WR;       // 8 rows (batch) x 516 floats

    const int tid  = threadIdx.x;
    const int bid  = blockIdx.x;
    const int cg   = bid & 15;
    const int grp  = bid >> 4;
    const int j0   = cg * 32;
    const int b0   = grp * 8;
    const int col  = tid >> 3;       // 0..31  (warp = 4 cols x 8 batches)
    const int bsub = tid & 7;        // 0..7
    const int b    = b0 + bsub;
    const int j    = j0 + col;

    // one-time: W_hh slice (96 rows x 512, coalesced gmem read)
    for (int idx = tid; idx < 96 * 512; idx += NT_REC) {
        int row = idx >> 9;          // g*32+col
        int k   = idx & 511;
        int g   = row >> 5;
        int c   = row & 31;
        Ws[row * WR + k] = Whh[(size_t)(g * HID + j0 + c) * HID + k];
    }
    for (int idx = tid; idx < 8 * WR; idx += NT_REC) hs[idx] = 0.f;

    const float bhr = bhh[j];
    const float bhz = bhh[HID + j];
    const float bhn = bhh[2 * HID + j];

    const float* wr = Ws + col * WR;
    const float* wz = Ws + (32 + col) * WR;
    const float* wn = Ws + (64 + col) * WR;
    const float* hb = hs + bsub * WR;

    const size_t xofs = (size_t)b * GATES3 + j;
    float xr = xg[xofs];
    float xz = xg[xofs + HID];
    float xn = xg[xofs + 2 * HID];

    float hp = 0.f;   // own h, in regs
    __syncthreads();

    for (int t = 0; t < T_STEPS; ++t) {
        if (t > 0) {
            // group barrier: all 16 blocks of this group posted step t
            if (tid < 16) {
                const unsigned* fp = &g_flags[grp * 16 + tid];
                unsigned v;
                do {
                    asm volatile("ld.acquire.gpu.global.u32 %0, [%1];" : "=r"(v) : "l"(fp));
                } while (v < (unsigned)t);
            }
            __syncthreads();
            // stage 16 KB of h for this group's 8 batches
            const float* hsrc = g_hx + (size_t)(t & 1) * BATCH * HID;
#pragma unroll
            for (int i = 0; i < 4; ++i) {
                int idx = tid + i * 256;
                int bb  = idx >> 7;
                int kq  = idx & 127;
                float4 v = __ldcg((const float4*)(hsrc + (size_t)(b0 + bb) * HID + kq * 4));
                *(float4*)(hs + bb * WR + kq * 4) = v;
            }
            __syncthreads();
        }

        // prefetch next step's xg early: LDG latency hides under the FMA loop
        float nxr = 0.f, nxz = 0.f, nxn = 0.f;
        if (t + 1 < T_STEPS) {
            const float* xp = xg + (size_t)(t + 1) * BATCH * GATES3 + xofs;
            nxr = __ldg(xp);
            nxz = __ldg(xp + HID);
            nxn = __ldg(xp + 2 * HID);
        }

        // full-k dot, FFMA2 packed along k: 3 gates x 1 col x 1 batch
        float2 r0 = {0, 0}, r1 = {0, 0};
        float2 z0 = {0, 0}, z1 = {0, 0};
        float2 n0 = {0, 0}, n1 = {0, 0};
#pragma unroll 8
        for (int k = 0; k < HID; k += 8) {
            float4 h0 = *(const float4*)(hb + k);
            float4 h1 = *(const float4*)(hb + k + 4);
            float4 a0 = *(const float4*)(wr + k);
            float4 a1 = *(const float4*)(wr + k + 4);
            float4 c0 = *(const float4*)(wz + k);
            float4 c1 = *(const float4*)(wz + k + 4);
            float4 d0 = *(const float4*)(wn + k);
            float4 d1 = *(const float4*)(wn + k + 4);
            r0 = ffma2(make_float2(a0.x, a0.y), make_float2(h0.x, h0.y), r0);
            r1 = ffma2(make_float2(a0.z, a0.w), make_float2(h0.z, h0.w), r1);
            z0 = ffma2(make_float2(c0.x, c0.y), make_float2(h0.x, h0.y), z0);
            z1 = ffma2(make_float2(c0.z, c0.w), make_float2(h0.z, h0.w), z1);
            n0 = ffma2(make_float2(d0.x, d0.y), make_float2(h0.x, h0.y), n0);
            n1 = ffma2(make_float2(d0.z, d0.w), make_float2(h0.z, h0.w), n1);
            r0 = ffma2(make_float2(a1.x, a1.y), make_float2(h1.x, h1.y), r0);
            r1 = ffma2(make_float2(a1.z, a1.w), make_float2(h1.z, h1.w), r1);
            z0 = ffma2(make_float2(c1.x, c1.y), make_float2(h1.x, h1.y), z0);
            z1 = ffma2(make_float2(c1.z, c1.w), make_float2(h1.z, h1.w), z1);
            n0 = ffma2(make_float2(d1.x, d1.y), make_float2(h1.x, h1.y), n0);
            n1 = ffma2(make_float2(d1.z, d1.w), make_float2(h1.z, h1.w), n1);
        }
        float hr = r0.x + r0.y + r1.x + r1.y + bhr;
        float hz = z0.x + z0.y + z1.x + z1.y + bhz;
        float hn = n0.x + n0.y + n1.x + n1.y + bhn;

        // finalize (fully parallel, all 256 threads)
        float rg = sigmoidf_(xr + hr);
        float zg = sigmoidf_(xz + hz);
        float ng = tanhf(xn + rg * hn);
        hp = (1.f - zg) * ng + zg * hp;

        // publish h FIRST (critical path), then flag
        g_hx[(size_t)((t + 1) & 1) * BATCH * HID + (size_t)b * HID + j] = hp;
        __syncthreads();
        if (tid == 0 && t < T_STEPS - 1) {
            __threadfence();
            asm volatile("st.global.cg.u32 [%0], %1;"
                         :: "l"(&g_flags[bid]), "r"((unsigned)(t + 1)) : "memory");
        }

        // off critical path: y store, hn store
        y[((size_t)t * BATCH + b) * HID + j] = hp;
        if (t == T_STEPS - 1) hn_out[(size_t)b * HID + j] = hp;

        xr = nxr; xz = nxz; xn = nxn;
    }

    // end-of-launch: group gen-barrier (replay-safe), reset own flag
    __syncthreads();
    if (tid == 0) {
        unsigned gen = g_end_gen[grp];
        __threadfence();
        if (atomicAdd(&g_end_cnt[grp], 1u) == 15u) {
            g_end_cnt[grp] = 0u;
            __threadfence();
            g_end_gen[grp] = gen + 1u;
        } else {
            while (g_end_gen[grp] == gen) { __nanosleep(32); }
        }
        g_flags[bid] = 0u;
        __threadfence();
    }
}

// ---------------- launch ----------------
extern "C" void kernel_launch(void* const* d_in, const int* in_sizes, int n_in,
                              void* d_out, int out_size) {
    const float* x    = (const float*)d_in[0];
    const float* Wih0 = (const float*)d_in[1];
    const float* Whh0 = (const float*)d_in[2];
    const float* bih0 = (const float*)d_in[3];
    const float* bhh0 = (const float*)d_in[4];
    const float* Wih1 = (const float*)d_in[5];
    const float* Whh1 = (const float*)d_in[6];
    const float* bih1 = (const float*)d_in[7];
    const float* bhh1 = (const float*)d_in[8];

    float* out = (float*)d_out;
    float* y1  = out;
    float* hn0 = out + (size_t)T_STEPS * BATCH * HID;
    float* hn1 = hn0 + BATCH * HID;

    float *xg, *y0;
    cudaGetSymbolAddress((void**)&xg, g_xg);
    cudaGetSymbolAddress((void**)&y0, g_y0);

    const int rec_smem = (96 * WR + 8 * WR) * 4;  // 214,656 B
    cudaFuncSetAttribute(gru_rec_kernel, cudaFuncAttributeMaxDynamicSharedMemorySize, rec_smem);

    dim3 ggrid(12, 256);

    gemm_bias_kernel<<<ggrid, 256>>>(x, Wih0, bih0, xg, 256);
    gru_rec_kernel<<<NB_REC, NT_REC, rec_smem>>>(xg, Whh0, bhh0, y0, hn0);
    gemm_bias_kernel<<<ggrid, 256>>>(y0, Wih1, bih1, xg, 512);
    gru_rec_kernel<<<NB_REC, NT_REC, rec_smem>>>(xg, Whh1, bhh1, y1, hn1);
}